// round 12
// baseline (speedup 1.0000x reference)
#include <cuda_runtime.h>
#include <cuda_fp16.h>
#include <cstdint>

// EdgeNetwork hybrid: two engines with disjoint bottlenecks run concurrently.
//  Engine A (HMMA, tensor/latency-bound): msg[e] = C[e] @ W, C built in regs.
//  Engine B (T-gather, L2-byte-bound):    msg[e] = sum_k b[e,k]*T[nb][k][:] + Tb.
//  Block-level dispatch: bid < NB_H -> engine A on edges [0, E_h);
//                        else       -> engine B on edges [E_h, n_edges).

#define MAX_ATOMS 20000
#define NW 8
#define NPAIR 2
#define EPC (NW * NPAIR * 32)   // 512 edges per HMMA CTA

__device__ __half g_Th[MAX_ATOMS * 256];   // [a][k][i] fp16, 512B/atom
__device__ float  g_Tb[MAX_ATOMS * 16];    // [a][i] fp32
__device__ __half g_Wimg[16 * 280];        // padded W image for HMMA B-frags

__device__ __forceinline__ void red_add_v2(float* addr, float x, float y) {
    asm volatile("red.global.add.v2.f32 [%0], {%1,%2};"
                 :: "l"(addr), "f"(x), "f"(y) : "memory");
}
__device__ __forceinline__ void red_add_v4(float* addr, float4 v) {
    asm volatile("red.global.add.v4.f32 [%0], {%1,%2,%3,%4};"
                 :: "l"(addr), "f"(v.x), "f"(v.y), "f"(v.z), "f"(v.w)
                 : "memory");
}
__device__ __forceinline__ unsigned hmul2u(__half2 a, __half2 b) {
    __half2 r = __hmul2(a, b);
    return *reinterpret_cast<unsigned*>(&r);
}
__device__ __forceinline__ void mma16816(float& d0, float& d1, float& d2,
                                         float& d3, unsigned a0, unsigned a1,
                                         unsigned a2, unsigned a3,
                                         unsigned b0, unsigned b1) {
    asm volatile(
        "mma.sync.aligned.m16n8k16.row.col.f32.f16.f16.f32 "
        "{%0,%1,%2,%3}, {%4,%5,%6,%7}, {%8,%9}, {%0,%1,%2,%3};"
        : "+f"(d0), "+f"(d1), "+f"(d2), "+f"(d3)
        : "r"(a0), "r"(a1), "r"(a2), "r"(a3), "r"(b0), "r"(b1));
}

// ---------------- Phase 1: precompute T/Tb + W image + zero out -------------
#define APB 16
__global__ void precompute_all(const float* __restrict__ A,
                               const float* __restrict__ Kmat,
                               const float* __restrict__ bias,
                               float* __restrict__ out,
                               int n_atoms) {
    __shared__ float  Ks[16 * 272];   // [k][i*17 + j] conflict-free
    __shared__ float  Bs[272];
    __shared__ float4 As4[APB * 4];

    const int tid = threadIdx.x;
    const int k = tid >> 4;
    const int i = tid & 15;

    {   // zero this block's slice of out
        int o = blockIdx.x * 256 + tid;
        if (o < n_atoms * 16) out[o] = 0.f;
    }

    #pragma unroll
    for (int r = 0; r < 16; ++r) {
        float v = Kmat[r * 256 + tid];
        Ks[r * 272 + k * 17 + i] = v;
    }
    Bs[k * 17 + i] = bias[tid];

    const int a0 = blockIdx.x * APB;
    if (tid < APB * 4) {
        int gidx4 = a0 * 4 + tid;
        As4[tid] = (gidx4 * 4 < n_atoms * 16)
                 ? reinterpret_cast<const float4*>(A)[gidx4]
                 : make_float4(0.f, 0.f, 0.f, 0.f);
    }
    __syncthreads();

    float kv[16];
    #pragma unroll
    for (int j = 0; j < 16; ++j)
        kv[j] = Ks[k * 272 + i * 17 + j];

    #pragma unroll
    for (int la = 0; la < APB; ++la) {
        int a = a0 + la;
        if (a >= n_atoms) break;
        float s = 0.f;
        #pragma unroll
        for (int c = 0; c < 4; ++c) {
            const float4 av = As4[la * 4 + c];
            s += kv[4 * c + 0] * av.x;
            s += kv[4 * c + 1] * av.y;
            s += kv[4 * c + 2] * av.z;
            s += kv[4 * c + 3] * av.w;
        }
        g_Th[(size_t)a * 256 + tid] = __float2half_rn(s);
    }

    {   // Tb: one value per thread
        const int la = tid >> 4;
        const int ib = tid & 15;
        const int a = a0 + la;
        if (a < n_atoms) {
            float s = 0.f;
            #pragma unroll
            for (int c = 0; c < 4; ++c) {
                const float4 av = As4[la * 4 + c];
                s += Bs[ib * 17 + 4 * c + 0] * av.x;
                s += Bs[ib * 17 + 4 * c + 1] * av.y;
                s += Bs[ib * 17 + 4 * c + 2] * av.z;
                s += Bs[ib * 17 + 4 * c + 3] * av.w;
            }
            g_Tb[a * 16 + ib] = s;
        }
    }

    // block 0 additionally builds the padded W image for the HMMA engine
    if (blockIdx.x == 0) {
        for (int idx = tid; idx < 16 * 272; idx += 256) {
            const int n = idx / 272;
            const int K = idx % 272;
            const int kk = K >> 4;
            const int j = K & 15;
            const float v = (kk < 16) ? Kmat[kk * 256 + n * 16 + j]
                                      : bias[n * 16 + j];
            g_Wimg[n * 280 + K] = __float2half_rn(v);
        }
    }
}

// ---------------- Phase 2: combined edge kernel ------------------------------
__global__ void __launch_bounds__(256)
edge_combined(const float* __restrict__ bond,
              const int* __restrict__ pairs,
              const float* __restrict__ A,
              float* __restrict__ out,
              int n_edges, int E_h, int NB_H) {
    __shared__ __half Wsm[16 * 280];
    __shared__ __half2 bbuf[NW][2][16][8];

    const int tid = threadIdx.x;

    if ((int)blockIdx.x < NB_H) {
        // ================= Engine A: HMMA (edges [0, E_h), E_h % 512 == 0) ==
        const int lane = tid & 31;
        const int w = tid >> 5;
        const int g = lane >> 2;
        const int t = lane & 3;

        {   // stage W image (verbatim uint4 copy)
            const uint4* src = reinterpret_cast<const uint4*>(g_Wimg);
            uint4* dst = reinterpret_cast<uint4*>(Wsm);
            for (int i = tid; i < 560; i += 256) dst[i] = src[i];
        }
        __syncthreads();

        const int warp_base = blockIdx.x * EPC + w * (NPAIR * 32);

        for (int pr_i = 0; pr_i < NPAIR; ++pr_i) {
            const int pbase = warp_base + pr_i * 32;

            #pragma unroll
            for (int tl = 0; tl < 2; ++tl) {
                const int ebase = pbase + tl * 16;
                const int et = lane >> 1;
                const int hcol = lane & 1;
                const float4* b4 = reinterpret_cast<const float4*>(bond)
                                 + (size_t)(ebase + et) * 4 + hcol * 2;
                const float4 f0 = b4[0];
                const float4 f1 = b4[1];
                float bf[8] = {f0.x, f0.y, f0.z, f0.w, f1.x, f1.y, f1.z, f1.w};
                __half* bb = reinterpret_cast<__half*>(bbuf[w][tl]);
                const int r = et & 7;
                const int hi = et >> 3;
                #pragma unroll
                for (int c = 0; c < 8; ++c) {
                    const int s = hcol * 8 + c;
                    bb[(s * 8 + r) * 2 + hi] = __float2half_rn(bf[c]);
                }
            }
            __syncwarp();

            int dst0[2], dst1[2];
            __half2 hal0[2], hah0[2], hal1[2], hah1[2];
            #pragma unroll
            for (int tl = 0; tl < 2; ++tl) {
                const int ebase = pbase + tl * 16;
                const int2 p0 = reinterpret_cast<const int2*>(pairs)[ebase + g];
                const int2 p1 = reinterpret_cast<const int2*>(pairs)[ebase + g + 8];
                dst0[tl] = p0.x;
                dst1[tl] = p1.x;
                const float* A0 = A + (size_t)p0.y * 16;
                const float* A1 = A + (size_t)p1.y * 16;
                const float2 al0 = *reinterpret_cast<const float2*>(A0 + 2 * t);
                const float2 ah0 = *reinterpret_cast<const float2*>(A0 + 8 + 2 * t);
                const float2 al1 = *reinterpret_cast<const float2*>(A1 + 2 * t);
                const float2 ah1 = *reinterpret_cast<const float2*>(A1 + 8 + 2 * t);
                hal0[tl] = __floats2half2_rn(al0.x, al0.y);
                hah0[tl] = __floats2half2_rn(ah0.x, ah0.y);
                hal1[tl] = __floats2half2_rn(al1.x, al1.y);
                hah1[tl] = __floats2half2_rn(ah1.x, ah1.y);
            }

            float d[2][8];
            #pragma unroll
            for (int tl = 0; tl < 2; ++tl)
                #pragma unroll
                for (int q = 0; q < 8; ++q) d[tl][q] = 0.f;

            #pragma unroll
            for (int s = 0; s < 17; ++s) {
                const __half* Wr0 = Wsm + g * 280 + s * 16 + t * 2;
                const __half* Wr1 = Wsm + (g + 8) * 280 + s * 16 + t * 2;
                const unsigned b00 = *reinterpret_cast<const unsigned*>(Wr0);
                const unsigned b01 = *reinterpret_cast<const unsigned*>(Wr0 + 8);
                const unsigned b10 = *reinterpret_cast<const unsigned*>(Wr1);
                const unsigned b11 = *reinterpret_cast<const unsigned*>(Wr1 + 8);

                #pragma unroll
                for (int tl = 0; tl < 2; ++tl) {
                    __half2 bl, bh;
                    if (s < 16) {
                        const __half2 b2 = bbuf[w][tl][s][g];
                        bl = __half2half2(__low2half(b2));
                        bh = __half2half2(__high2half(b2));
                    } else {
                        bl = __floats2half2_rn(1.f, 1.f);
                        bh = bl;
                    }
                    const unsigned a0 = hmul2u(bl, hal0[tl]);
                    const unsigned a1 = hmul2u(bh, hal1[tl]);
                    const unsigned a2 = hmul2u(bl, hah0[tl]);
                    const unsigned a3 = hmul2u(bh, hah1[tl]);
                    mma16816(d[tl][0], d[tl][1], d[tl][2], d[tl][3],
                             a0, a1, a2, a3, b00, b01);
                    mma16816(d[tl][4], d[tl][5], d[tl][6], d[tl][7],
                             a0, a1, a2, a3, b10, b11);
                }
            }

            #pragma unroll
            for (int tl = 0; tl < 2; ++tl) {
                float* o0 = out + (size_t)dst0[tl] * 16;
                float* o1 = out + (size_t)dst1[tl] * 16;
                red_add_v2(o0 + 2 * t, d[tl][0], d[tl][1]);
                red_add_v2(o0 + 8 + 2 * t, d[tl][4], d[tl][5]);
                red_add_v2(o1 + 2 * t, d[tl][2], d[tl][3]);
                red_add_v2(o1 + 8 + 2 * t, d[tl][6], d[tl][7]);
            }
            __syncwarp();
        }
    } else {
        // ================= Engine B: fp16 T-gather (edges [E_h, n_edges)) ===
        const int gid = ((int)blockIdx.x - NB_H) * 256 + tid;
        int e = E_h + (gid >> 3);
        const int t = gid & 7;
        const bool valid = (e < n_edges);
        if (!valid) e = n_edges - 1;

        const int2 pr = reinterpret_cast<const int2*>(pairs)[e];

        const float b0 = bond[e * 16 + t];
        const float b1 = bond[e * 16 + 8 + t];
        __half2 hb0 = __float2half2_rn(b0);
        __half2 hb1 = __float2half2_rn(b1);
        const unsigned u0 = *reinterpret_cast<unsigned*>(&hb0);
        const unsigned u1 = *reinterpret_cast<unsigned*>(&hb1);

        const __half* Trow = g_Th + (size_t)pr.y * 256;

        __half2 acc[4];
        acc[0] = acc[1] = acc[2] = acc[3] = __float2half2_rn(0.f);

        #pragma unroll
        for (int q = 0; q < 4; ++q) {
            const int src = (q & 1) * 4 + (t >> 1);
            unsigned bu = __shfl_sync(0xffffffffu, (q < 2) ? u0 : u1, src, 8);
            const __half2 bk2 = *reinterpret_cast<__half2*>(&bu);
            const uint4 tv = *reinterpret_cast<const uint4*>(Trow + q * 64 + t * 8);
            const __half2* h = reinterpret_cast<const __half2*>(&tv);
            #pragma unroll
            for (int p = 0; p < 4; ++p)
                acc[p] = __hfma2(h[p], bk2, acc[p]);
        }

        #pragma unroll
        for (int p = 0; p < 4; ++p) {
            unsigned u = *reinterpret_cast<unsigned*>(&acc[p]);
            unsigned o = __shfl_xor_sync(0xffffffffu, u, 2, 8);
            acc[p] = __hadd2(acc[p], *reinterpret_cast<__half2*>(&o));
            u = *reinterpret_cast<unsigned*>(&acc[p]);
            o = __shfl_xor_sync(0xffffffffu, u, 4, 8);
            acc[p] = __hadd2(acc[p], *reinterpret_cast<__half2*>(&o));
        }

        if (valid && t < 4) {
            const int qidx = (t & 1) * 2 + (t >> 1);
            const float4 tb =
                reinterpret_cast<const float4*>(g_Tb + pr.y * 16)[qidx];
            const float2 f0 = __half22float2(acc[(t < 2) ? 0 : 2]);
            const float2 f1 = __half22float2(acc[(t < 2) ? 1 : 3]);
            float4 v = make_float4(f0.x + tb.x, f0.y + tb.y,
                                   f1.x + tb.z, f1.y + tb.w);
            red_add_v4(out + pr.x * 16 + qidx * 4, v);
        }
    }
}

extern "C" void kernel_launch(void* const* d_in, const int* in_sizes, int n_in,
                              void* d_out, int out_size) {
    const float* A     = (const float*)d_in[0];  // atom_features [n_atoms,16]
    const float* bond  = (const float*)d_in[1];  // bond_features [n_edges,16]
    const int*   pairs = (const int*)  d_in[2];  // pair_indices  [n_edges,2]
    const float* Kmat  = (const float*)d_in[3];  // kernel [16,256]
    const float* bias  = (const float*)d_in[4];  // bias [256]
    float* out = (float*)d_out;                  // [n_atoms,16]

    const int n_atoms = in_sizes[0] / 16;
    const int n_edges = in_sizes[2] / 2;

    // split: HMMA engine takes ~half, rounded to a multiple of 512
    const int E_h = ((n_edges / 2) / EPC) * EPC;
    const int NB_H = E_h / EPC;
    const int E_t = n_edges - E_h;
    const int NB_T = (E_t * 8 + 255) / 256;

    precompute_all<<<(n_atoms + APB - 1) / APB, 256>>>(A, Kmat, bias, out, n_atoms);
    edge_combined<<<NB_H + NB_T, 256>>>(bond, pairs, A, out, n_edges, E_h, NB_H);
}

// round 13
// speedup vs baseline: 1.3545x; 1.3545x over previous
#include <cuda_runtime.h>
#include <cuda_fp16.h>
#include <cstdint>

// EdgeNetwork as warp-level HMMA GEMM (mma.sync.m16n8k16):
//   msg[e,i] = sum_{K=0..271} C[e,K] * W[K,i],  K = k*16+j
//   C[e,K]   = b'[e,k] * A[nb_e, j],  b' = [b[e], 1.0]  (k=16 row folds bias)
//   W[k*16+j, i] = Kmat[k, i*16+j]  (k<16),  bias[i*16+j] (k=16)
// Warp = 2 interleaved 16-edge tiles (4 independent HMMA streams / k-step),
// W image prebuilt (verbatim smem copy, no ALU), EPC=256 -> grid 2500.

#define NW 8                  // warps per CTA
#define EPC (NW * 32)         // 256 edges per CTA

// prebuilt fp16 W image, padded row stride 280 halfs (bank-conflict-free LDS)
__device__ __half g_Wimg[16 * 280];

__device__ __forceinline__ void red_add_v2(float* addr, float x, float y) {
    asm volatile("red.global.add.v2.f32 [%0], {%1,%2};"
                 :: "l"(addr), "f"(x), "f"(y) : "memory");
}

__device__ __forceinline__ unsigned hmul2u(__half2 a, __half2 b) {
    __half2 r = __hmul2(a, b);
    return *reinterpret_cast<unsigned*>(&r);
}

__device__ __forceinline__ void mma16816(float& d0, float& d1, float& d2,
                                         float& d3, unsigned a0, unsigned a1,
                                         unsigned a2, unsigned a3,
                                         unsigned b0, unsigned b1) {
    asm volatile(
        "mma.sync.aligned.m16n8k16.row.col.f32.f16.f16.f32 "
        "{%0,%1,%2,%3}, {%4,%5,%6,%7}, {%8,%9}, {%0,%1,%2,%3};"
        : "+f"(d0), "+f"(d1), "+f"(d2), "+f"(d3)
        : "r"(a0), "r"(a1), "r"(a2), "r"(a3), "r"(b0), "r"(b1));
}

// ---------------- setup: zero output everywhere; block 0 builds W image -----
__global__ void build_w_zero(const float* __restrict__ Kmat,
                             const float* __restrict__ bias,
                             float* __restrict__ out, int n_out4) {
    const int gid = blockIdx.x * blockDim.x + threadIdx.x;
    if (gid < n_out4)
        reinterpret_cast<float4*>(out)[gid] = make_float4(0.f, 0.f, 0.f, 0.f);
    if (blockIdx.x == 0) {
        const int tid = threadIdx.x;  // 256
        for (int idx = tid; idx < 16 * 272; idx += 256) {
            const int i = idx / 272;          // output index (n)
            const int K = idx % 272;          // K position
            const int k = K >> 4;
            const int j = K & 15;
            const float v = (k < 16) ? Kmat[k * 256 + i * 16 + j]
                                     : bias[i * 16 + j];
            g_Wimg[i * 280 + K] = __float2half_rn(v);
        }
    }
}

// ---------------- main edge kernel -------------------------------------------
__global__ void __launch_bounds__(NW * 32)
edge_hmma(const float* __restrict__ bond,
          const int* __restrict__ pairs,
          const float* __restrict__ A,
          float* __restrict__ out,
          int n_edges) {
    __shared__ __half Wsm[16 * 280];            // 8960 B
    __shared__ __half2 bbuf[NW][2][16][8];      // 8 KB

    const int tid = threadIdx.x;
    const int lane = tid & 31;
    const int w = tid >> 5;
    const int g = lane >> 2;      // fragment row group (0..7)
    const int t = lane & 3;       // fragment quad (0..3)

    // stage W image (verbatim, 560 uint4 — no ALU)
    {
        const uint4* src = reinterpret_cast<const uint4*>(g_Wimg);
        uint4* dst = reinterpret_cast<uint4*>(Wsm);
        for (int i = tid; i < 560; i += NW * 32) dst[i] = src[i];
    }
    __syncthreads();

    const int warp_base = blockIdx.x * EPC + w * 32;

    // ---- stage bond rows for both tiles ----
    #pragma unroll
    for (int tl = 0; tl < 2; ++tl) {
        const int ebase = warp_base + tl * 16;
        const int et = lane >> 1;
        const int hcol = lane & 1;          // 0 -> s 0..7, 1 -> s 8..15
        const int esrc = min(ebase + et, n_edges - 1);
        const float4* b4 = reinterpret_cast<const float4*>(bond)
                         + (size_t)esrc * 4 + hcol * 2;
        const float4 f0 = b4[0];
        const float4 f1 = b4[1];
        float bf[8] = {f0.x, f0.y, f0.z, f0.w, f1.x, f1.y, f1.z, f1.w};
        __half* bb = reinterpret_cast<__half*>(bbuf[w][tl]);
        const int r = et & 7;
        const int hi = et >> 3;
        #pragma unroll
        for (int c = 0; c < 8; ++c) {
            const int s = hcol * 8 + c;
            bb[(s * 8 + r) * 2 + hi] = __float2half_rn(bf[c]);
        }
    }
    __syncwarp();

    // ---- per-thread edges / A fragments for both tiles ----
    int dst0[2], dst1[2];
    __half2 hal0[2], hah0[2], hal1[2], hah1[2];
    #pragma unroll
    for (int tl = 0; tl < 2; ++tl) {
        const int ebase = warp_base + tl * 16;
        const int e0 = min(ebase + g, n_edges - 1);
        const int e1 = min(ebase + g + 8, n_edges - 1);
        const int2 p0 = reinterpret_cast<const int2*>(pairs)[e0];
        const int2 p1 = reinterpret_cast<const int2*>(pairs)[e1];
        dst0[tl] = p0.x;
        dst1[tl] = p1.x;
        const float* A0 = A + (size_t)p0.y * 16;
        const float* A1 = A + (size_t)p1.y * 16;
        const float2 al0 = *reinterpret_cast<const float2*>(A0 + 2 * t);
        const float2 ah0 = *reinterpret_cast<const float2*>(A0 + 8 + 2 * t);
        const float2 al1 = *reinterpret_cast<const float2*>(A1 + 2 * t);
        const float2 ah1 = *reinterpret_cast<const float2*>(A1 + 8 + 2 * t);
        hal0[tl] = __floats2half2_rn(al0.x, al0.y);
        hah0[tl] = __floats2half2_rn(ah0.x, ah0.y);
        hal1[tl] = __floats2half2_rn(al1.x, al1.y);
        hah1[tl] = __floats2half2_rn(ah1.x, ah1.y);
    }

    float d[2][8];
    #pragma unroll
    for (int tl = 0; tl < 2; ++tl)
        #pragma unroll
        for (int q = 0; q < 8; ++q) d[tl][q] = 0.f;

    #pragma unroll
    for (int s = 0; s < 17; ++s) {
        // B fragments: shared by both tiles (depend only on s, g, t)
        const __half* Wr0 = Wsm + g * 280 + s * 16 + t * 2;
        const __half* Wr1 = Wsm + (g + 8) * 280 + s * 16 + t * 2;
        const unsigned b00 = *reinterpret_cast<const unsigned*>(Wr0);
        const unsigned b01 = *reinterpret_cast<const unsigned*>(Wr0 + 8);
        const unsigned b10 = *reinterpret_cast<const unsigned*>(Wr1);
        const unsigned b11 = *reinterpret_cast<const unsigned*>(Wr1 + 8);

        #pragma unroll
        for (int tl = 0; tl < 2; ++tl) {
            __half2 bl, bh;
            if (s < 16) {
                const __half2 b2 = bbuf[w][tl][s][g];  // (b[e0][s], b[e1][s])
                bl = __half2half2(__low2half(b2));
                bh = __half2half2(__high2half(b2));
            } else {
                bl = __floats2half2_rn(1.f, 1.f);      // bias row
                bh = bl;
            }
            const unsigned a0 = hmul2u(bl, hal0[tl]);
            const unsigned a1 = hmul2u(bh, hal1[tl]);
            const unsigned a2 = hmul2u(bl, hah0[tl]);
            const unsigned a3 = hmul2u(bh, hah1[tl]);

            mma16816(d[tl][0], d[tl][1], d[tl][2], d[tl][3],
                     a0, a1, a2, a3, b00, b01);
            mma16816(d[tl][4], d[tl][5], d[tl][6], d[tl][7],
                     a0, a1, a2, a3, b10, b11);
        }
    }

    // ---- epilogue ----
    #pragma unroll
    for (int tl = 0; tl < 2; ++tl) {
        const int ebase = warp_base + tl * 16;
        const int e0 = ebase + g;
        const int e1 = ebase + g + 8;
        if (e0 < n_edges) {
            float* o = out + (size_t)dst0[tl] * 16;
            red_add_v2(o + 2 * t, d[tl][0], d[tl][1]);
            red_add_v2(o + 8 + 2 * t, d[tl][4], d[tl][5]);
        }
        if (e1 < n_edges) {
            float* o = out + (size_t)dst1[tl] * 16;
            red_add_v2(o + 2 * t, d[tl][2], d[tl][3]);
            red_add_v2(o + 8 + 2 * t, d[tl][6], d[tl][7]);
        }
    }
}

extern "C" void kernel_launch(void* const* d_in, const int* in_sizes, int n_in,
                              void* d_out, int out_size) {
    const float* A     = (const float*)d_in[0];  // atom_features [n_atoms,16]
    const float* bond  = (const float*)d_in[1];  // bond_features [n_edges,16]
    const int*   pairs = (const int*)  d_in[2];  // pair_indices  [n_edges,2]
    const float* Kmat  = (const float*)d_in[3];  // kernel [16,256]
    const float* bias  = (const float*)d_in[4];  // bias [256]
    float* out = (float*)d_out;                  // [n_atoms,16]

    const int n_edges = in_sizes[2] / 2;
    const int n_out4 = out_size / 4;

    // one launch: zero out[] everywhere, block 0 also builds the W image
    build_w_zero<<<(n_out4 + 255) / 256, 256>>>(Kmat, bias, out, n_out4);

    const int blocks = (n_edges + EPC - 1) / EPC;
    edge_hmma<<<blocks, NW * 32>>>(bond, pairs, A, out, n_edges);
}